// round 8
// baseline (speedup 1.0000x reference)
#include <cuda_runtime.h>
#include <cuda_bf16.h>

#define BATCH 8
#define SEQ   8192
#define DMODEL 1024
#define NTOK (BATCH * SEQ)
#define FULL 0xFFFFFFFFu
#define BLOCKS_PER_ROW (SEQ / 32)   // 256 (32 tokens per 1024-thread block)

// Scratch: sortable keys per token. Active key = monotone uint transform of
// score (always > 0); inactive = 0.
__device__ unsigned int g_keys[NTOK];
// Per-row completion counters (zero-initialized; reset in-kernel each launch).
__device__ int g_cnt[BATCH];

__device__ __forceinline__ int block_reduce_int(int v, int* red)
{
    int lane = threadIdx.x & 31, wid = threadIdx.x >> 5;
#pragma unroll
    for (int o = 16; o; o >>= 1) v += __shfl_xor_sync(FULL, v, o);
    if (lane == 0) red[wid] = v;
    __syncthreads();
    if (wid == 0) {
        int x = (lane < 32) ? red[lane] : 0;
#pragma unroll
        for (int o = 16; o; o >>= 1) x += __shfl_xor_sync(FULL, x, o);
        if (lane == 0) red[0] = x;
    }
    __syncthreads();
    int r = red[0];
    __syncthreads();
    return r;
}

// ---------------------------------------------------------------------------
// Fused kernel: warp-per-token scoring (HBM stream), then the LAST block to
// finish a row runs that row's exact variable top-k select while other rows
// keep streaming. Select cost is hidden under the 43us HBM stream except the
// final row's tail.
// ---------------------------------------------------------------------------
__global__ void __launch_bounds__(1024)
fused_kernel(const float* __restrict__ hidden,
             const unsigned int* __restrict__ mask,
             const float* __restrict__ w,
             const float* __restrict__ bias,
             float* __restrict__ out)
{
    const int tid  = threadIdx.x;
    const int lane = tid & 31;
    const int wid  = tid >> 5;

    // ---------------- Phase 1: score my 32 tokens (one per warp) ----------
    const int token = blockIdx.x * 32 + wid;
    const int row   = token >> 13;            // / SEQ

    {
        const float4* hp = reinterpret_cast<const float4*>(hidden + (size_t)token * DMODEL);
        const float4* wp = reinterpret_cast<const float4*>(w);
        float acc = 0.0f;
#pragma unroll
        for (int i = 0; i < 8; i++) {
            float4 a = hp[lane + i * 32];
            float4 c = wp[lane + i * 32];
            acc += a.x * c.x + a.y * c.y + a.z * c.z + a.w * c.w;
        }
#pragma unroll
        for (int o = 16; o; o >>= 1) acc += __shfl_xor_sync(FULL, acc, o);

        if (lane == 0) {
            float s = acc + bias[0];
            unsigned int u = __float_as_uint(s);
            u = (u & 0x80000000u) ? ~u : (u | 0x80000000u);   // order-preserving
            g_keys[token] = (mask[token] != 0u) ? u : 0u;      // inactive -> 0
        }
    }

    // ---------------- Arrival: am I the last block of this row? -----------
    __shared__ int isLast;
    __threadfence();            // publish key writes device-wide
    __syncthreads();
    if (tid == 0) {
        int old = atomicAdd(&g_cnt[row], 1);
        isLast = (old == BLOCKS_PER_ROW - 1);
        if (isLast) g_cnt[row] = 0;            // reset for next graph replay
    }
    __syncthreads();
    if (!isLast) return;
    __threadfence();            // acquire side: see all rows' key writes

    // ---------------- Phase 2: select for `row` (1024 threads) ------------
    __shared__ int hist[256];
    __shared__ int sfx[257];
    __shared__ int wsum[32];
    __shared__ int red[32];
    __shared__ int bcast[2];

    const unsigned int* keys = g_keys + row * SEQ;
    float* o = out + row * SEQ;

    // Each thread owns contiguous indices [tid*8, tid*8+8). __ldcg bypasses
    // L1 so we read the L2-coherent values written by other SMs.
    const uint4 k0 = __ldcg(reinterpret_cast<const uint4*>(keys) + tid * 2);
    const uint4 k1 = __ldcg(reinterpret_cast<const uint4*>(keys) + tid * 2 + 1);
    unsigned int v[8] = {k0.x, k0.y, k0.z, k0.w, k1.x, k1.y, k1.z, k1.w};

    int na = 0;
#pragma unroll
    for (int i = 0; i < 8; i++) na += (v[i] != 0u);
    const int n_active = block_reduce_int(na, red);

    if (n_active == 0) {
        float4 z = make_float4(0.f, 0.f, 0.f, 0.f);
        reinterpret_cast<float4*>(o)[tid * 2]     = z;
        reinterpret_cast<float4*>(o)[tid * 2 + 1] = z;
        return;
    }
    const int k = (n_active + 1) >> 1;   // max(1, ceil(n/2)) for n >= 1

    // ---- MSB-first radix select for the k-th largest key t ----
    unsigned int prefix = 0;
    int krem = k;
#pragma unroll
    for (int shift = 24; shift >= 0; shift -= 8) {
        if (tid < 256) hist[tid] = 0;
        if (tid == 256) sfx[256] = 0;
        __syncthreads();

        const unsigned int pmask = (shift == 24) ? 0u : (FULL << (shift + 8));
#pragma unroll
        for (int i = 0; i < 8; i++) {
            bool p = (v[i] & pmask) == prefix;
            unsigned int bin = (v[i] >> shift) & 255u;
            unsigned int tag = p ? bin : 0x100u;
            unsigned int peers = __match_any_sync(FULL, tag);
            if (p && ((int)(__ffs(peers) - 1) == lane))
                atomicAdd(&hist[bin], __popc(peers));   // one atomic per group
        }
        __syncthreads();

        // Parallel suffix scan: sfx[bin] = sum_{j>=bin} hist[j]
        int sval = 0;
        if (tid < 256) {
            sval = hist[255 - tid];
#pragma unroll
            for (int d = 1; d < 32; d <<= 1) {
                int n2 = __shfl_up_sync(FULL, sval, d);
                if (lane >= d) sval += n2;
            }
            if (lane == 31) wsum[wid] = sval;
        }
        __syncthreads();
        if (tid < 8) {
            int x = wsum[tid];
#pragma unroll
            for (int d = 1; d < 8; d <<= 1) {
                int n2 = __shfl_up_sync(0xFFu, x, d);
                if (tid >= d) x += n2;
            }
            wsum[tid] = x;
        }
        __syncthreads();
        if (tid < 256) sfx[255 - tid] = sval + ((wid > 0) ? wsum[wid - 1] : 0);
        __syncthreads();
        if (tid < 256) {
            int bin = 255 - tid;
            int S = sfx[bin], Sn = sfx[bin + 1];
            if (S >= krem && Sn < krem) {   // unique boundary (S monotone)
                bcast[0] = bin;
                bcast[1] = krem - Sn;
            }
        }
        __syncthreads();
        prefix |= ((unsigned int)bcast[0]) << shift;
        krem = bcast[1];
        __syncthreads();
    }
    const unsigned int t = prefix;

    // ---- strictly greater count -> equals to admit ----
    int cgt = 0;
#pragma unroll
    for (int i = 0; i < 8; i++) cgt += (v[i] > t);
    const int count_gt = block_reduce_int(cgt, red);
    const int mneed = k - count_gt;   // >= 1

    // ---- stable rank among equals: exclusive block scan (thread order ==
    //      index order thanks to contiguous ownership) ----
    int le = 0;
#pragma unroll
    for (int i = 0; i < 8; i++) le += (v[i] == t);
    int s = le;
#pragma unroll
    for (int d = 1; d < 32; d <<= 1) {
        int n2 = __shfl_up_sync(FULL, s, d);
        if (lane >= d) s += n2;
    }
    if (lane == 31) wsum[wid] = s;
    __syncthreads();
    if (wid == 0) {
        int x = wsum[lane];
#pragma unroll
        for (int d = 1; d < 32; d <<= 1) {
            int n2 = __shfl_up_sync(FULL, x, d);
            if (lane >= d) x += n2;
        }
        wsum[lane] = x;
    }
    __syncthreads();
    int eq_rank = s - le + ((wid > 0) ? wsum[wid - 1] : 0);

    // ---- emit keep mask as float 1.0/0.0 ----
    float r8[8];
#pragma unroll
    for (int i = 0; i < 8; i++) {
        bool keep;
        if (v[i] > t)       keep = true;
        else if (v[i] == t) { keep = (eq_rank < mneed); eq_rank++; }
        else                keep = false;
        r8[i] = keep ? 1.0f : 0.0f;
    }
    reinterpret_cast<float4*>(o)[tid * 2]     = make_float4(r8[0], r8[1], r8[2], r8[3]);
    reinterpret_cast<float4*>(o)[tid * 2 + 1] = make_float4(r8[4], r8[5], r8[6], r8[7]);
}

extern "C" void kernel_launch(void* const* d_in, const int* in_sizes, int n_in,
                              void* d_out, int out_size)
{
    // Bind inputs by element count (all distinct):
    //   hidden 67108864, mask 65536, w 1024, bias 1
    const float*        hidden = nullptr;
    const unsigned int* mask   = nullptr;
    const float*        w      = nullptr;
    const float*        bias   = nullptr;
    for (int i = 0; i < n_in; i++) {
        if      (in_sizes[i] == 67108864) hidden = (const float*)d_in[i];
        else if (in_sizes[i] == 65536)    mask   = (const unsigned int*)d_in[i];
        else if (in_sizes[i] == 1024)     w      = (const float*)d_in[i];
        else if (in_sizes[i] == 1)        bias   = (const float*)d_in[i];
    }
    float* out = (float*)d_out;

    fused_kernel<<<NTOK / 32, 1024>>>(hidden, mask, w, bias, out);
}

// round 9
// speedup vs baseline: 1.3789x; 1.3789x over previous
#include <cuda_runtime.h>
#include <cuda_bf16.h>

#define BATCH 8
#define SEQ   8192
#define DMODEL 1024
#define NTOK (BATCH * SEQ)
#define FULL 0xFFFFFFFFu

// Scratch: sortable keys per token. Active key = monotone uint transform of
// score (always >= 0x00800000 for finite scores); inactive = 0.
__device__ unsigned int g_keys[NTOK];

// ---------------------------------------------------------------------------
// Kernel 1: scores[b,s] = dot(hidden[b,s,:], w) + bias ; key = sortable(score)
// One warp per token; streams 256 MB of hidden once (HBM-bound, ~6 TB/s).
// __ldcs = evict-first so the stream does not flush g_keys out of L2.
// ---------------------------------------------------------------------------
__global__ void __launch_bounds__(256)
score_kernel(const float* __restrict__ hidden,
             const unsigned int* __restrict__ mask,
             const float* __restrict__ w,
             const float* __restrict__ bias)
{
    int warp = (blockIdx.x * blockDim.x + threadIdx.x) >> 5;
    int lane = threadIdx.x & 31;
    if (warp >= NTOK) return;

    const float4* hp = reinterpret_cast<const float4*>(hidden + (size_t)warp * DMODEL);
    const float4* wp = reinterpret_cast<const float4*>(w);

    float acc = 0.0f;
#pragma unroll
    for (int i = 0; i < 8; i++) {
        float4 a = __ldcs(hp + lane + i * 32);   // streaming, evict-first
        float4 c = wp[lane + i * 32];            // hot in L1
        acc += a.x * c.x + a.y * c.y + a.z * c.z + a.w * c.w;
    }
#pragma unroll
    for (int o = 16; o; o >>= 1) acc += __shfl_xor_sync(FULL, acc, o);

    if (lane == 0) {
        float s = acc + bias[0];
        unsigned int u = __float_as_uint(s);
        u = (u & 0x80000000u) ? ~u : (u | 0x80000000u);  // order-preserving
        g_keys[warp] = (mask[warp] != 0u) ? u : 0u;      // inactive -> 0
    }
}

// ---------------------------------------------------------------------------
// Kernel 2: per-row exact variable top-k, stable lowest-index tie break.
// One block/row, 1024 threads, 8 contiguous keys/thread in registers.
// 3-pass radix select [11,11,10] with plain SMEM atomics and a parallel
// suffix scan (2 bins/thread for 2048-bin passes).
// ---------------------------------------------------------------------------
__device__ __forceinline__ int block_reduce_int(int v, int* red)
{
    int lane = threadIdx.x & 31, wid = threadIdx.x >> 5;
#pragma unroll
    for (int o = 16; o; o >>= 1) v += __shfl_xor_sync(FULL, v, o);
    if (lane == 0) red[wid] = v;
    __syncthreads();
    if (wid == 0) {
        int x = (lane < 32) ? red[lane] : 0;
#pragma unroll
        for (int o = 16; o; o >>= 1) x += __shfl_xor_sync(FULL, x, o);
        if (lane == 0) red[0] = x;
    }
    __syncthreads();
    int r = red[0];
    __syncthreads();
    return r;
}

// Suffix-scan hist[0..NB) into sfx[0..NB]; sfx[NB]=0 must be preset.
// Then locate boundary bin: sfx[b] >= krem > sfx[b+1]; write {b, krem-sfx[b+1]}.
template<int NB>
__device__ __forceinline__ void suffix_scan_and_pick(
    int* hist, int* sfx, int* wsum, int krem, int* bcast)
{
    const int tid = threadIdx.x, lane = tid & 31, wid = tid >> 5;
    constexpr int BPT = NB / 1024;
    const int base = NB - 1 - tid * BPT;

    int local = 0;
#pragma unroll
    for (int i = 0; i < BPT; i++) local += hist[base - i];

    int s = local;
#pragma unroll
    for (int d = 1; d < 32; d <<= 1) {
        int n2 = __shfl_up_sync(FULL, s, d);
        if (lane >= d) s += n2;
    }
    if (lane == 31) wsum[wid] = s;
    __syncthreads();
    if (wid == 0) {
        int x = wsum[lane];
#pragma unroll
        for (int d = 1; d < 32; d <<= 1) {
            int n2 = __shfl_up_sync(FULL, x, d);
            if (lane >= d) x += n2;
        }
        wsum[lane] = x;
    }
    __syncthreads();
    int run = s - local + ((wid > 0) ? wsum[wid - 1] : 0);   // exclusive
#pragma unroll
    for (int i = 0; i < BPT; i++) {
        int b = base - i;
        run += hist[b];
        sfx[b] = run;
    }
    __syncthreads();
#pragma unroll
    for (int i = 0; i < BPT; i++) {
        int b = base - i;
        int S = sfx[b], Sn = sfx[b + 1];
        if (S >= krem && Sn < krem) {        // unique (S monotone nonincreasing)
            bcast[0] = b;
            bcast[1] = krem - Sn;
        }
    }
    __syncthreads();
}

__global__ void __launch_bounds__(1024)
select_kernel(float* __restrict__ out)
{
    __shared__ int hist[2048];
    __shared__ int sfx[2049];
    __shared__ int wsum[32];
    __shared__ int red[32];
    __shared__ int bcast[2];

    const int b = blockIdx.x, tid = threadIdx.x;
    const int lane = tid & 31, wid = tid >> 5;
    const unsigned int* keys = g_keys + b * SEQ;
    float* o = out + b * SEQ;

    // Contiguous ownership: indices [tid*8, tid*8+8)
    const uint4 k0 = __ldcg(reinterpret_cast<const uint4*>(keys) + tid * 2);
    const uint4 k1 = __ldcg(reinterpret_cast<const uint4*>(keys) + tid * 2 + 1);
    unsigned int v[8] = {k0.x, k0.y, k0.z, k0.w, k1.x, k1.y, k1.z, k1.w};

    int na = 0;
#pragma unroll
    for (int i = 0; i < 8; i++) na += (v[i] != 0u);
    const int n_active = block_reduce_int(na, red);

    if (n_active == 0) {
        float4 z = make_float4(0.f, 0.f, 0.f, 0.f);
        reinterpret_cast<float4*>(o)[tid * 2]     = z;
        reinterpret_cast<float4*>(o)[tid * 2 + 1] = z;
        return;
    }
    const int k = (n_active + 1) >> 1;   // max(1, ceil(n/2)), n >= 1

    unsigned int prefix = 0;
    int krem = k;

    // ---- Pass 1: bits [31:21], 2048 bins, all keys participate ----
    for (int j = tid; j < 2048; j += 1024) hist[j] = 0;
    if (tid == 0) sfx[2048] = 0;
    __syncthreads();
#pragma unroll
    for (int i = 0; i < 8; i++)
        atomicAdd(&hist[v[i] >> 21], 1);
    __syncthreads();
    suffix_scan_and_pick<2048>(hist, sfx, wsum, krem, bcast);
    prefix = ((unsigned int)bcast[0]) << 21;
    krem = bcast[1];
    __syncthreads();

    // ---- Pass 2: bits [20:10], 2048 bins, prefix-matching keys only ----
    for (int j = tid; j < 2048; j += 1024) hist[j] = 0;
    __syncthreads();
#pragma unroll
    for (int i = 0; i < 8; i++)
        if ((v[i] & 0xFFE00000u) == prefix)
            atomicAdd(&hist[(v[i] >> 10) & 2047u], 1);
    __syncthreads();
    suffix_scan_and_pick<2048>(hist, sfx, wsum, krem, bcast);
    prefix |= ((unsigned int)bcast[0]) << 10;
    krem = bcast[1];
    __syncthreads();

    // ---- Pass 3: bits [9:0], 1024 bins ----
    for (int j = tid; j < 2048; j += 1024) hist[j] = 0;   // clears 1024 used + spare
    if (tid == 0) sfx[1024] = 0;
    __syncthreads();
#pragma unroll
    for (int i = 0; i < 8; i++)
        if ((v[i] & 0xFFFFFC00u) == prefix)
            atomicAdd(&hist[v[i] & 1023u], 1);
    __syncthreads();
    suffix_scan_and_pick<1024>(hist, sfx, wsum, krem, bcast);
    const unsigned int t = prefix | (unsigned int)bcast[0];
    __syncthreads();

    // ---- strictly-greater count -> number of equals to admit ----
    int cgt = 0;
#pragma unroll
    for (int i = 0; i < 8; i++) cgt += (v[i] > t);
    const int count_gt = block_reduce_int(cgt, red);
    const int mneed = k - count_gt;   // >= 1

    // ---- stable rank among equals: exclusive block scan (thread order ==
    //      index order thanks to contiguous ownership) ----
    int le = 0;
#pragma unroll
    for (int i = 0; i < 8; i++) le += (v[i] == t);
    int s = le;
#pragma unroll
    for (int d = 1; d < 32; d <<= 1) {
        int n2 = __shfl_up_sync(FULL, s, d);
        if (lane >= d) s += n2;
    }
    if (lane == 31) wsum[wid] = s;
    __syncthreads();
    if (wid == 0) {
        int x = wsum[lane];
#pragma unroll
        for (int d = 1; d < 32; d <<= 1) {
            int n2 = __shfl_up_sync(FULL, x, d);
            if (lane >= d) x += n2;
        }
        wsum[lane] = x;
    }
    __syncthreads();
    int eq_rank = s - le + ((wid > 0) ? wsum[wid - 1] : 0);

    // ---- emit keep mask as float 1.0/0.0 ----
    float r8[8];
#pragma unroll
    for (int i = 0; i < 8; i++) {
        bool keep;
        if (v[i] > t)       keep = true;
        else if (v[i] == t) { keep = (eq_rank < mneed); eq_rank++; }
        else                keep = false;
        r8[i] = keep ? 1.0f : 0.0f;
    }
    reinterpret_cast<float4*>(o)[tid * 2]     = make_float4(r8[0], r8[1], r8[2], r8[3]);
    reinterpret_cast<float4*>(o)[tid * 2 + 1] = make_float4(r8[4], r8[5], r8[6], r8[7]);
}

extern "C" void kernel_launch(void* const* d_in, const int* in_sizes, int n_in,
                              void* d_out, int out_size)
{
    // Bind inputs by element count (all distinct):
    //   hidden 67108864, mask 65536, w 1024, bias 1
    const float*        hidden = nullptr;
    const unsigned int* mask   = nullptr;
    const float*        w      = nullptr;
    const float*        bias   = nullptr;
    for (int i = 0; i < n_in; i++) {
        if      (in_sizes[i] == 67108864) hidden = (const float*)d_in[i];
        else if (in_sizes[i] == 65536)    mask   = (const unsigned int*)d_in[i];
        else if (in_sizes[i] == 1024)     w      = (const float*)d_in[i];
        else if (in_sizes[i] == 1)        bias   = (const float*)d_in[i];
    }
    float* out = (float*)d_out;

    score_kernel<<<NTOK / 8, 256>>>(hidden, mask, w, bias);
    select_kernel<<<BATCH, 1024>>>(out);
}